// round 6
// baseline (speedup 1.0000x reference)
#include <cuda_runtime.h>
#include <math.h>

#define BATCH 128
#define TIME  4096
#define T0    2048
#define T1    1024
#define T2    512
#define C0    32
#define C1    64
#define C2    128
#define HID   256
#define G3H   768
#define RMS_EPS 1e-6f

// ---------------- scratch (device globals; no runtime allocation) -------
__device__ float g_h0[(size_t)BATCH * T0 * C0];
__device__ float g_h1[(size_t)BATCH * T1 * C1];
__device__ float g_h2[(size_t)BATCH * T2 * C2];
__device__ float g_xi[(size_t)BATCH * T2 * G3H];
__device__ float g_hseq[(size_t)BATCH * T2 * HID];
__device__ float g_wn[HID * HID];
__device__ float g_wht[G3H * HID];   // transposed gru_wh: [col j][k]

__device__ __forceinline__ float gelu_tanh(float x) {
    float u = 0.7978845608028654f * (x + 0.044715f * x * x * x);
    return 0.5f * x * (1.0f + tanhf(u));
}
__device__ __forceinline__ float sigm(float x) { return 1.0f / (1.0f + expf(-x)); }

// ======================= prep: weight-normalized proj matrix ============
__global__ void k_wnorm(const float* __restrict__ v, const float* __restrict__ g) {
    int j = threadIdx.x;                      // column 0..255
    float ss = 0.f;
    for (int k = 0; k < HID; k++) { float t = v[k * HID + j]; ss = fmaf(t, t, ss); }
    float inv = g[j] / (sqrtf(ss) + 1e-8f);
    for (int k = 0; k < HID; k++) g_wn[k * HID + j] = v[k * HID + j] * inv;
}

// ======================= prep: transpose gru_wh ==========================
__global__ void k_twh(const float* __restrict__ wh) {
    int j = blockIdx.x;                       // 0..767
    int k = threadIdx.x;                      // 0..255
    g_wht[(size_t)j * HID + k] = wh[(size_t)k * G3H + j];
}

// ======================= conv0: [128,4096] -> [128,2048,32] =============
__global__ void k_conv0(const float* __restrict__ x, const float* __restrict__ w,
                        const float* __restrict__ bias, const float* __restrict__ scale) {
    __shared__ float w_s[9 * C0];
    __shared__ float b_s[C0], s_s[C0];
    int tid = threadIdx.x;
    for (int i = tid; i < 9 * C0; i += 256) w_s[i] = w[i];
    if (tid < C0) { b_s[tid] = bias[tid]; s_s[tid] = scale[tid]; }
    __syncthreads();

    int b = blockIdx.y;
    int t = blockIdx.x * 256 + tid;           // grid.x = 8 -> t < 2048
    const float* xrow = x + (size_t)b * TIME;
    float xv[9];
    int base = 2 * t - 3;
#pragma unroll
    for (int k = 0; k < 9; k++) {
        int p = base + k;
        xv[k] = (p >= 0 && p < TIME) ? xrow[p] * 1e20f : 0.0f;
    }
    float acc[C0];
#pragma unroll
    for (int c = 0; c < C0; c++) acc[c] = b_s[c];
#pragma unroll
    for (int k = 0; k < 9; k++) {
        float xk = xv[k];
#pragma unroll
        for (int c = 0; c < C0; c++) acc[c] = fmaf(xk, w_s[k * C0 + c], acc[c]);
    }
    float ss = 0.f;
#pragma unroll
    for (int c = 0; c < C0; c++) ss = fmaf(acc[c], acc[c], ss);
    float rs = rsqrtf(ss * (1.0f / C0) + RMS_EPS);
    float* orow = g_h0 + ((size_t)b * T0 + t) * C0;
#pragma unroll
    for (int c = 0; c < C0; c++) orow[c] = gelu_tanh(acc[c] * rs * s_s[c]);
}

// ======================= conv1: [128,2048,32] -> [128,1024,64] ==========
// block: (b, 32-t tile). 256 thr: cg=tid&15 -> 4 cout, tg=tid>>4 -> 2 t.
__global__ void k_conv1(const float* __restrict__ w, const float* __restrict__ bias,
                        const float* __restrict__ scale) {
    __shared__ float in_s[71][C0];            // ~9 KB
    __shared__ float4 wk[C0 * C1 / 4];        // 8 KB
    __shared__ float b_s[C1], s_s[C1];
    int tid = threadIdx.x;
    int b = blockIdx.y, t0 = blockIdx.x * 32;
    int base = 2 * t0 - 3;
    for (int i = tid; i < 71 * C0; i += 256) {
        int pl = i >> 5, ci = i & 31;
        int p = base + pl;
        in_s[pl][ci] = (p >= 0 && p < T0) ? g_h0[((size_t)b * T0 + p) * C0 + ci] : 0.0f;
    }
    if (tid < C1) { b_s[tid] = bias[tid]; s_s[tid] = scale[tid]; }

    int cg = tid & 15, tg = tid >> 4;
    float acc[2][4] = {};
    for (int k = 0; k < 9; k++) {
        __syncthreads();
        const float4* ws = (const float4*)(w + (size_t)k * C0 * C1);
        for (int i = tid; i < C0 * C1 / 4; i += 256) wk[i] = ws[i];
        __syncthreads();
#pragma unroll 8
        for (int ci = 0; ci < C0; ci++) {
            float4 wv = wk[ci * 16 + cg];
#pragma unroll
            for (int i = 0; i < 2; i++) {
                float xv = in_s[2 * (tg * 2 + i) + k][ci];
                acc[i][0] = fmaf(xv, wv.x, acc[i][0]);
                acc[i][1] = fmaf(xv, wv.y, acc[i][1]);
                acc[i][2] = fmaf(xv, wv.z, acc[i][2]);
                acc[i][3] = fmaf(xv, wv.w, acc[i][3]);
            }
        }
    }
#pragma unroll
    for (int i = 0; i < 2; i++) {
        float ss = 0.f;
#pragma unroll
        for (int j = 0; j < 4; j++) { acc[i][j] += b_s[cg * 4 + j]; ss = fmaf(acc[i][j], acc[i][j], ss); }
        ss += __shfl_xor_sync(0xffffffffu, ss, 1);
        ss += __shfl_xor_sync(0xffffffffu, ss, 2);
        ss += __shfl_xor_sync(0xffffffffu, ss, 4);
        ss += __shfl_xor_sync(0xffffffffu, ss, 8);
        float rs = rsqrtf(ss * (1.0f / C1) + RMS_EPS);
        int t = t0 + tg * 2 + i;
        float4 o;
        o.x = gelu_tanh(acc[i][0] * rs * s_s[cg * 4 + 0]);
        o.y = gelu_tanh(acc[i][1] * rs * s_s[cg * 4 + 1]);
        o.z = gelu_tanh(acc[i][2] * rs * s_s[cg * 4 + 2]);
        o.w = gelu_tanh(acc[i][3] * rs * s_s[cg * 4 + 3]);
        *(float4*)&g_h1[((size_t)b * T1 + t) * C1 + cg * 4] = o;
    }
}

// ======================= conv2: [128,1024,64] -> [128,512,128] ==========
// block: (b, 16-t tile). 256 thr: cg=tid&31 -> 4 cout, tg=tid>>5 -> 2 t.
__global__ void k_conv2(const float* __restrict__ w, const float* __restrict__ bias,
                        const float* __restrict__ scale) {
    __shared__ float in_s[39][C1];            // ~10 KB
    __shared__ float4 wk[C1 * C2 / 4];        // 32 KB
    __shared__ float b_s[C2], s_s[C2];
    int tid = threadIdx.x;
    int b = blockIdx.y, t0 = blockIdx.x * 16;
    int base = 2 * t0 - 3;
    for (int i = tid; i < 39 * C1; i += 256) {
        int pl = i >> 6, ci = i & 63;
        int p = base + pl;
        in_s[pl][ci] = (p >= 0 && p < T1) ? g_h1[((size_t)b * T1 + p) * C1 + ci] : 0.0f;
    }
    if (tid < C2) { b_s[tid] = bias[tid]; s_s[tid] = scale[tid]; }

    int cg = tid & 31, tg = tid >> 5;
    float acc[2][4] = {};
    for (int k = 0; k < 9; k++) {
        __syncthreads();
        const float4* ws = (const float4*)(w + (size_t)k * C1 * C2);
        for (int i = tid; i < C1 * C2 / 4; i += 256) wk[i] = ws[i];
        __syncthreads();
#pragma unroll 8
        for (int ci = 0; ci < C1; ci++) {
            float4 wv = wk[ci * 32 + cg];
#pragma unroll
            for (int i = 0; i < 2; i++) {
                float xv = in_s[2 * (tg * 2 + i) + k][ci];
                acc[i][0] = fmaf(xv, wv.x, acc[i][0]);
                acc[i][1] = fmaf(xv, wv.y, acc[i][1]);
                acc[i][2] = fmaf(xv, wv.z, acc[i][2]);
                acc[i][3] = fmaf(xv, wv.w, acc[i][3]);
            }
        }
    }
#pragma unroll
    for (int i = 0; i < 2; i++) {
        float ss = 0.f;
#pragma unroll
        for (int j = 0; j < 4; j++) { acc[i][j] += b_s[cg * 4 + j]; ss = fmaf(acc[i][j], acc[i][j], ss); }
        ss += __shfl_xor_sync(0xffffffffu, ss, 1);
        ss += __shfl_xor_sync(0xffffffffu, ss, 2);
        ss += __shfl_xor_sync(0xffffffffu, ss, 4);
        ss += __shfl_xor_sync(0xffffffffu, ss, 8);
        ss += __shfl_xor_sync(0xffffffffu, ss, 16);
        float rs = rsqrtf(ss * (1.0f / C2) + RMS_EPS);
        int t = t0 + tg * 2 + i;
        float4 o;
        o.x = gelu_tanh(acc[i][0] * rs * s_s[cg * 4 + 0]);
        o.y = gelu_tanh(acc[i][1] * rs * s_s[cg * 4 + 1]);
        o.z = gelu_tanh(acc[i][2] * rs * s_s[cg * 4 + 2]);
        o.w = gelu_tanh(acc[i][3] * rs * s_s[cg * 4 + 3]);
        *(float4*)&g_h2[((size_t)b * T2 + t) * C2 + cg * 4] = o;
    }
}

// ======================= xi GEMM: [65536,128] @ [128,768] + bi ==========
__global__ void k_xi(const float* __restrict__ wi, const float* __restrict__ bi) {
    __shared__ float a_s[64][65];
    __shared__ float b_s[64][64];
    int tid = threadIdx.x;
    int m0 = blockIdx.x * 64, n0 = blockIdx.y * 64;
    int tx = tid & 15, ty = tid >> 4;
    float acc[4][4] = {};
    for (int kc = 0; kc < 128; kc += 64) {
        __syncthreads();
        for (int i = tid; i < 4096; i += 256) {
            int r = i >> 6, c = i & 63;
            a_s[r][c] = g_h2[(size_t)(m0 + r) * C2 + kc + c];
            b_s[r][c] = wi[(size_t)(kc + r) * G3H + n0 + c];
        }
        __syncthreads();
#pragma unroll 8
        for (int k = 0; k < 64; k++) {
            float a[4], bb[4];
#pragma unroll
            for (int i = 0; i < 4; i++) a[i] = a_s[ty + 16 * i][k];
#pragma unroll
            for (int j = 0; j < 4; j++) bb[j] = b_s[k][tx + 16 * j];
#pragma unroll
            for (int i = 0; i < 4; i++)
#pragma unroll
                for (int j = 0; j < 4; j++) acc[i][j] = fmaf(a[i], bb[j], acc[i][j]);
        }
    }
#pragma unroll
    for (int i = 0; i < 4; i++)
#pragma unroll
        for (int j = 0; j < 4; j++)
            g_xi[(size_t)(m0 + ty + 16 * i) * G3H + n0 + tx + 16 * j] = acc[i][j] + bi[n0 + tx + 16 * j];
}

// ======================= GRU scan: 64 CTAs x 2 batch rows ================
__global__ void k_gru(const float* __restrict__ bhn) {
    __shared__ float4 hs[2][HID / 4];
    int tid = threadIdx.x;
    int r0 = blockIdx.x * 2;
    float* h0p = (float*)hs[0];
    float* h1p = (float*)hs[1];
    h0p[tid] = 0.f; h1p[tid] = 0.f;
    __syncthreads();
    float bn = bhn[tid];
    const float4* wr = (const float4*)(g_wht + (size_t)tid * HID);
    const float4* wz = (const float4*)(g_wht + (size_t)(HID + tid) * HID);
    const float4* wn = (const float4*)(g_wht + (size_t)(2 * HID + tid) * HID);
    const float* xi0 = g_xi + (size_t)r0 * T2 * G3H;
    const float* xi1 = xi0 + (size_t)T2 * G3H;
    float* o0 = g_hseq + (size_t)r0 * T2 * HID;
    float* o1 = o0 + (size_t)T2 * HID;

    for (int t = 0; t < T2; t++) {
        float a0r = 0.f, a0z = 0.f, a0n = 0.f, a1r = 0.f, a1z = 0.f, a1n = 0.f;
#pragma unroll 4
        for (int k = 0; k < HID / 4; k++) {
            float4 h0 = hs[0][k], h1 = hs[1][k];
            float4 w = wr[k];
            a0r = fmaf(h0.x, w.x, fmaf(h0.y, w.y, fmaf(h0.z, w.z, fmaf(h0.w, w.w, a0r))));
            a1r = fmaf(h1.x, w.x, fmaf(h1.y, w.y, fmaf(h1.z, w.z, fmaf(h1.w, w.w, a1r))));
            w = wz[k];
            a0z = fmaf(h0.x, w.x, fmaf(h0.y, w.y, fmaf(h0.z, w.z, fmaf(h0.w, w.w, a0z))));
            a1z = fmaf(h1.x, w.x, fmaf(h1.y, w.y, fmaf(h1.z, w.z, fmaf(h1.w, w.w, a1z))));
            w = wn[k];
            a0n = fmaf(h0.x, w.x, fmaf(h0.y, w.y, fmaf(h0.z, w.z, fmaf(h0.w, w.w, a0n))));
            a1n = fmaf(h1.x, w.x, fmaf(h1.y, w.y, fmaf(h1.z, w.z, fmaf(h1.w, w.w, a1n))));
        }
        const float* p0 = xi0 + (size_t)t * G3H;
        const float* p1 = xi1 + (size_t)t * G3H;
        float hp0 = h0p[tid], hp1 = h1p[tid];
        float r = sigm(p0[tid] + a0r);
        float z = sigm(p0[HID + tid] + a0z);
        float n = tanhf(p0[2 * HID + tid] + r * (a0n + bn));
        float hn0 = (1.f - z) * n + z * hp0;
        r = sigm(p1[tid] + a1r);
        z = sigm(p1[HID + tid] + a1z);
        n = tanhf(p1[2 * HID + tid] + r * (a1n + bn));
        float hn1 = (1.f - z) * n + z * hp1;
        __syncthreads();
        h0p[tid] = hn0; h1p[tid] = hn1;
        o0[(size_t)t * HID + tid] = hn0;
        o1[(size_t)t * HID + tid] = hn1;
        __syncthreads();
    }
}

// ======================= proj GEMM + bias + row L2-norm =================
// 32 rows x 256 cols per block; lane owns cols cg+32j; warp covers a full row.
__global__ void k_proj(const float* __restrict__ pb, float* __restrict__ out) {
    __shared__ float a_s[32][33];
    __shared__ float b_s[32][HID];
    int tid = threadIdx.x;
    int m0 = blockIdx.x * 32;
    int cg = tid & 31, rg = tid >> 5;
    float acc[4][8] = {};
    for (int kc = 0; kc < HID; kc += 32) {
        __syncthreads();
        for (int i = tid; i < 32 * 32; i += 256) {
            int r = i >> 5, c = i & 31;
            a_s[r][c] = g_hseq[(size_t)(m0 + r) * HID + kc + c];
        }
        for (int i = tid; i < 32 * HID; i += 256) {
            int r = i >> 8, c = i & 255;
            b_s[r][c] = g_wn[(size_t)(kc + r) * HID + c];
        }
        __syncthreads();
#pragma unroll 4
        for (int k = 0; k < 32; k++) {
            float a[4], bb[8];
#pragma unroll
            for (int i = 0; i < 4; i++) a[i] = a_s[rg * 4 + i][k];
#pragma unroll
            for (int j = 0; j < 8; j++) bb[j] = b_s[k][cg + 32 * j];
#pragma unroll
            for (int i = 0; i < 4; i++)
#pragma unroll
                for (int j = 0; j < 8; j++) acc[i][j] = fmaf(a[i], bb[j], acc[i][j]);
        }
    }
#pragma unroll
    for (int i = 0; i < 4; i++) {
        float ss = 0.f;
#pragma unroll
        for (int j = 0; j < 8; j++) {
            acc[i][j] += pb[cg + 32 * j];
            ss = fmaf(acc[i][j], acc[i][j], ss);
        }
        ss += __shfl_xor_sync(0xffffffffu, ss, 1);
        ss += __shfl_xor_sync(0xffffffffu, ss, 2);
        ss += __shfl_xor_sync(0xffffffffu, ss, 4);
        ss += __shfl_xor_sync(0xffffffffu, ss, 8);
        ss += __shfl_xor_sync(0xffffffffu, ss, 16);
        float nrm = sqrtf(ss);
        float sc = (nrm > 1e-6f) ? 1.0f / (nrm + 1e-8f) : 1.0f;
        size_t row = (size_t)(m0 + rg * 4 + i);
#pragma unroll
        for (int j = 0; j < 8; j++) out[row * HID + cg + 32 * j] = acc[i][j] * sc;
    }
}

// ======================= launcher =======================================
extern "C" void kernel_launch(void* const* d_in, const int* in_sizes, int n_in,
                              void* d_out, int out_size) {
    (void)in_sizes; (void)n_in; (void)out_size;
    const float* x   = (const float*)d_in[0];
    const float* c0w = (const float*)d_in[1];
    const float* c0b = (const float*)d_in[2];
    const float* r0s = (const float*)d_in[3];
    const float* c1w = (const float*)d_in[4];
    const float* c1b = (const float*)d_in[5];
    const float* r1s = (const float*)d_in[6];
    const float* c2w = (const float*)d_in[7];
    const float* c2b = (const float*)d_in[8];
    const float* r2s = (const float*)d_in[9];
    const float* wi  = (const float*)d_in[10];
    const float* bi  = (const float*)d_in[11];
    const float* wh  = (const float*)d_in[12];
    const float* bhn = (const float*)d_in[13];
    const float* pv  = (const float*)d_in[14];
    const float* pg  = (const float*)d_in[15];
    const float* pb  = (const float*)d_in[16];
    float* out = (float*)d_out;

    k_wnorm<<<1, 256>>>(pv, pg);
    k_twh<<<G3H, 256>>>(wh);
    k_conv0<<<dim3(8, BATCH), 256>>>(x, c0w, c0b, r0s);
    k_conv1<<<dim3(32, BATCH), 256>>>(c1w, c1b, r1s);
    k_conv2<<<dim3(32, BATCH), 256>>>(c2w, c2b, r2s);
    k_xi<<<dim3(1024, 12), 256>>>(wi, bi);
    k_gru<<<64, 256>>>(bhn);
    k_proj<<<2048, 256>>>(pb, out);
}

// round 7
// speedup vs baseline: 5.5915x; 5.5915x over previous
#include <cuda_runtime.h>
#include <math.h>

#define BATCH 128
#define TIME  4096
#define T0    2048
#define T1    1024
#define T2    512
#define C0    32
#define C1    64
#define C2    128
#define HID   256
#define G3H   768
#define RMS_EPS 1e-6f

// ---------------- scratch (device globals; no runtime allocation) -------
__device__ float g_h0[(size_t)BATCH * T0 * C0];
__device__ float g_h1[(size_t)BATCH * T1 * C1];
__device__ float g_h2[(size_t)BATCH * T2 * C2];
__device__ float g_xi[(size_t)BATCH * T2 * G3H];
__device__ float g_hseq[(size_t)BATCH * T2 * HID];
__device__ float g_wn[HID * HID];

__device__ __forceinline__ float gelu_tanh(float x) {
    float u = 0.7978845608028654f * (x + 0.044715f * x * x * x);
    return 0.5f * x * (1.0f + tanhf(u));
}
__device__ __forceinline__ float sigm(float x) { return 1.0f / (1.0f + expf(-x)); }

// ---- packed f32x2 helpers (Blackwell) ----
__device__ __forceinline__ unsigned long long pk2(float lo, float hi) {
    unsigned long long d;
    asm("mov.b64 %0, {%1, %2};" : "=l"(d)
        : "r"(__float_as_uint(lo)), "r"(__float_as_uint(hi)));
    return d;
}
__device__ __forceinline__ unsigned long long f2fma(unsigned long long a,
                                                    unsigned long long b,
                                                    unsigned long long c) {
    unsigned long long d;
    asm("fma.rn.f32x2 %0, %1, %2, %3;" : "=l"(d) : "l"(a), "l"(b), "l"(c));
    return d;
}
__device__ __forceinline__ float2 upk(unsigned long long v) {
    unsigned lo, hi;
    asm("mov.b64 {%0, %1}, %2;" : "=r"(lo), "=r"(hi) : "l"(v));
    float2 r; r.x = __uint_as_float(lo); r.y = __uint_as_float(hi);
    return r;
}

// ======================= prep: weight-normalized proj matrix ============
__global__ void k_wnorm(const float* __restrict__ v, const float* __restrict__ g) {
    int j = threadIdx.x;                      // column 0..255
    float ss = 0.f;
    for (int k = 0; k < HID; k++) { float t = v[k * HID + j]; ss = fmaf(t, t, ss); }
    float inv = g[j] / (sqrtf(ss) + 1e-8f);
    for (int k = 0; k < HID; k++) g_wn[k * HID + j] = v[k * HID + j] * inv;
}

// ======================= conv0: [128,4096] -> [128,2048,32] =============
__global__ void k_conv0(const float* __restrict__ x, const float* __restrict__ w,
                        const float* __restrict__ bias, const float* __restrict__ scale) {
    __shared__ float w_s[9 * C0];
    __shared__ float b_s[C0], s_s[C0];
    int tid = threadIdx.x;
    for (int i = tid; i < 9 * C0; i += 256) w_s[i] = w[i];
    if (tid < C0) { b_s[tid] = bias[tid]; s_s[tid] = scale[tid]; }
    __syncthreads();

    int b = blockIdx.y;
    int t = blockIdx.x * 256 + tid;
    const float* xrow = x + (size_t)b * TIME;
    float xv[9];
    int base = 2 * t - 3;
#pragma unroll
    for (int k = 0; k < 9; k++) {
        int p = base + k;
        xv[k] = (p >= 0 && p < TIME) ? xrow[p] * 1e20f : 0.0f;
    }
    float acc[C0];
#pragma unroll
    for (int c = 0; c < C0; c++) acc[c] = b_s[c];
#pragma unroll
    for (int k = 0; k < 9; k++) {
        float xk = xv[k];
#pragma unroll
        for (int c = 0; c < C0; c++) acc[c] = fmaf(xk, w_s[k * C0 + c], acc[c]);
    }
    float ss = 0.f;
#pragma unroll
    for (int c = 0; c < C0; c++) ss = fmaf(acc[c], acc[c], ss);
    float rs = rsqrtf(ss * (1.0f / C0) + RMS_EPS);
    float* orow = g_h0 + ((size_t)b * T0 + t) * C0;
#pragma unroll
    for (int c = 0; c < C0; c++) orow[c] = gelu_tanh(acc[c] * rs * s_s[c]);
}

// ======================= conv1: [128,2048,32] -> [128,1024,64] ==========
__global__ void k_conv1(const float* __restrict__ w, const float* __restrict__ bias,
                        const float* __restrict__ scale) {
    __shared__ float in_s[71][C0];
    __shared__ float4 wk[C0 * C1 / 4];
    __shared__ float b_s[C1], s_s[C1];
    int tid = threadIdx.x;
    int b = blockIdx.y, t0 = blockIdx.x * 32;
    int base = 2 * t0 - 3;
    for (int i = tid; i < 71 * C0; i += 256) {
        int pl = i >> 5, ci = i & 31;
        int p = base + pl;
        in_s[pl][ci] = (p >= 0 && p < T0) ? g_h0[((size_t)b * T0 + p) * C0 + ci] : 0.0f;
    }
    if (tid < C1) { b_s[tid] = bias[tid]; s_s[tid] = scale[tid]; }

    int cg = tid & 15, tg = tid >> 4;
    float acc[2][4] = {};
    for (int k = 0; k < 9; k++) {
        __syncthreads();
        const float4* ws = (const float4*)(w + (size_t)k * C0 * C1);
        for (int i = tid; i < C0 * C1 / 4; i += 256) wk[i] = ws[i];
        __syncthreads();
#pragma unroll 8
        for (int ci = 0; ci < C0; ci++) {
            float4 wv = wk[ci * 16 + cg];
#pragma unroll
            for (int i = 0; i < 2; i++) {
                float xv = in_s[2 * (tg * 2 + i) + k][ci];
                acc[i][0] = fmaf(xv, wv.x, acc[i][0]);
                acc[i][1] = fmaf(xv, wv.y, acc[i][1]);
                acc[i][2] = fmaf(xv, wv.z, acc[i][2]);
                acc[i][3] = fmaf(xv, wv.w, acc[i][3]);
            }
        }
    }
#pragma unroll
    for (int i = 0; i < 2; i++) {
        float ss = 0.f;
#pragma unroll
        for (int j = 0; j < 4; j++) { acc[i][j] += b_s[cg * 4 + j]; ss = fmaf(acc[i][j], acc[i][j], ss); }
        ss += __shfl_xor_sync(0xffffffffu, ss, 1);
        ss += __shfl_xor_sync(0xffffffffu, ss, 2);
        ss += __shfl_xor_sync(0xffffffffu, ss, 4);
        ss += __shfl_xor_sync(0xffffffffu, ss, 8);
        float rs = rsqrtf(ss * (1.0f / C1) + RMS_EPS);
        int t = t0 + tg * 2 + i;
        float4 o;
        o.x = gelu_tanh(acc[i][0] * rs * s_s[cg * 4 + 0]);
        o.y = gelu_tanh(acc[i][1] * rs * s_s[cg * 4 + 1]);
        o.z = gelu_tanh(acc[i][2] * rs * s_s[cg * 4 + 2]);
        o.w = gelu_tanh(acc[i][3] * rs * s_s[cg * 4 + 3]);
        *(float4*)&g_h1[((size_t)b * T1 + t) * C1 + cg * 4] = o;
    }
}

// ======================= conv2: [128,1024,64] -> [128,512,128] ==========
__global__ void k_conv2(const float* __restrict__ w, const float* __restrict__ bias,
                        const float* __restrict__ scale) {
    __shared__ float in_s[39][C1];
    __shared__ float4 wk[C1 * C2 / 4];
    __shared__ float b_s[C2], s_s[C2];
    int tid = threadIdx.x;
    int b = blockIdx.y, t0 = blockIdx.x * 16;
    int base = 2 * t0 - 3;
    for (int i = tid; i < 39 * C1; i += 256) {
        int pl = i >> 6, ci = i & 63;
        int p = base + pl;
        in_s[pl][ci] = (p >= 0 && p < T1) ? g_h1[((size_t)b * T1 + p) * C1 + ci] : 0.0f;
    }
    if (tid < C2) { b_s[tid] = bias[tid]; s_s[tid] = scale[tid]; }

    int cg = tid & 31, tg = tid >> 5;
    float acc[2][4] = {};
    for (int k = 0; k < 9; k++) {
        __syncthreads();
        const float4* ws = (const float4*)(w + (size_t)k * C1 * C2);
        for (int i = tid; i < C1 * C2 / 4; i += 256) wk[i] = ws[i];
        __syncthreads();
#pragma unroll 8
        for (int ci = 0; ci < C1; ci++) {
            float4 wv = wk[ci * 32 + cg];
#pragma unroll
            for (int i = 0; i < 2; i++) {
                float xv = in_s[2 * (tg * 2 + i) + k][ci];
                acc[i][0] = fmaf(xv, wv.x, acc[i][0]);
                acc[i][1] = fmaf(xv, wv.y, acc[i][1]);
                acc[i][2] = fmaf(xv, wv.z, acc[i][2]);
                acc[i][3] = fmaf(xv, wv.w, acc[i][3]);
            }
        }
    }
#pragma unroll
    for (int i = 0; i < 2; i++) {
        float ss = 0.f;
#pragma unroll
        for (int j = 0; j < 4; j++) { acc[i][j] += b_s[cg * 4 + j]; ss = fmaf(acc[i][j], acc[i][j], ss); }
        ss += __shfl_xor_sync(0xffffffffu, ss, 1);
        ss += __shfl_xor_sync(0xffffffffu, ss, 2);
        ss += __shfl_xor_sync(0xffffffffu, ss, 4);
        ss += __shfl_xor_sync(0xffffffffu, ss, 8);
        ss += __shfl_xor_sync(0xffffffffu, ss, 16);
        float rs = rsqrtf(ss * (1.0f / C2) + RMS_EPS);
        int t = t0 + tg * 2 + i;
        float4 o;
        o.x = gelu_tanh(acc[i][0] * rs * s_s[cg * 4 + 0]);
        o.y = gelu_tanh(acc[i][1] * rs * s_s[cg * 4 + 1]);
        o.z = gelu_tanh(acc[i][2] * rs * s_s[cg * 4 + 2]);
        o.w = gelu_tanh(acc[i][3] * rs * s_s[cg * 4 + 3]);
        *(float4*)&g_h2[((size_t)b * T2 + t) * C2 + cg * 4] = o;
    }
}

// ======================= xi GEMM: [65536,128] @ [128,768] + bi ==========
__global__ void k_xi(const float* __restrict__ wi, const float* __restrict__ bi) {
    __shared__ float a_s[64][65];
    __shared__ float b_s[64][64];
    int tid = threadIdx.x;
    int m0 = blockIdx.x * 64, n0 = blockIdx.y * 64;
    int tx = tid & 15, ty = tid >> 4;
    float acc[4][4] = {};
    for (int kc = 0; kc < 128; kc += 64) {
        __syncthreads();
        for (int i = tid; i < 4096; i += 256) {
            int r = i >> 6, c = i & 63;
            a_s[r][c] = g_h2[(size_t)(m0 + r) * C2 + kc + c];
            b_s[r][c] = wi[(size_t)(kc + r) * G3H + n0 + c];
        }
        __syncthreads();
#pragma unroll 8
        for (int k = 0; k < 64; k++) {
            float a[4], bb[4];
#pragma unroll
            for (int i = 0; i < 4; i++) a[i] = a_s[ty + 16 * i][k];
#pragma unroll
            for (int j = 0; j < 4; j++) bb[j] = b_s[k][tx + 16 * j];
#pragma unroll
            for (int i = 0; i < 4; i++)
#pragma unroll
                for (int j = 0; j < 4; j++) acc[i][j] = fmaf(a[i], bb[j], acc[i][j]);
        }
    }
#pragma unroll
    for (int i = 0; i < 4; i++)
#pragma unroll
        for (int j = 0; j < 4; j++)
            g_xi[(size_t)(m0 + ty + 16 * i) * G3H + n0 + tx + 16 * j] = acc[i][j] + bi[n0 + tx + 16 * j];
}

// ======================= GRU: 4-CTA cluster, weights in smem ============
// Cluster of 4 CTAs owns 4 batch rows; rank r owns output columns [64r,64r+64).
// smem: w_s[3][256][64] (196608B) + h_s double-buffered [2][2 pair][258 pad]
// float2 (8256B) + partials [3][4][2][64] float2 (12288B) = 217152 B dynamic.
#define GRU_THREADS 384
#define GRU_SMEM (196608 + 8256 + 12288)

__global__ void __cluster_dims__(4, 1, 1) __launch_bounds__(GRU_THREADS, 1)
k_gru(const float* __restrict__ wh, const float* __restrict__ bhn) {
    extern __shared__ float smem[];
    float*  w_s  = smem;                         // [g][k][j]: g*16384 + k*64 + j
    float2* h_s  = (float2*)(smem + 49152);      // [buf][pair][k]: buf*516 + pair*258 + k
    float2* part = h_s + 1032;                   // [g][ks][pair][j]

    unsigned rank;
    asm("mov.u32 %0, %%cluster_ctarank;" : "=r"(rank));
    int tid = threadIdx.x;
    int cid = blockIdx.x >> 2;
    int r0  = cid * 4;                           // 4 batch rows per cluster
    int jg0 = (int)rank * 64;                    // this CTA's column slice

    // load this CTA's weight slice, coalesced from original [k][768] layout
    for (int i = tid; i < 3 * 256 * 64; i += GRU_THREADS) {
        int g = i >> 14, rem = i & 16383;
        int k = rem >> 6, j = rem & 63;
        w_s[i] = wh[(size_t)k * G3H + g * HID + jg0 + j];
    }
    for (int i = tid; i < 516; i += GRU_THREADS) h_s[i] = make_float2(0.f, 0.f);
    __syncthreads();
    asm volatile("barrier.cluster.arrive.aligned;" ::: "memory");
    asm volatile("barrier.cluster.wait.aligned;"   ::: "memory");

    // k-loop identity: 12 warps = (gate, k-slice); lanes = (row-pair, j-quad)
    int wid = tid >> 5, lane = tid & 31;
    int g = wid >> 2, ks = wid & 3;
    int pair = lane >> 4, jq = lane & 15;
    const float* wbase = w_s + g * 16384 + (ks * 64) * 64 + jq * 4;

    // epilogue identity: threads 0..255 = (row, j)
    int erow = tid >> 6, ej = tid & 63;
    int epair = erow >> 1, ehalf = erow & 1;
    bool epi = (tid < 256);
    float ebhn = 0.f;
    const float* xi_p = nullptr;
    float* o_p = nullptr;
    if (epi) {
        ebhn = bhn[jg0 + ej];
        xi_p = g_xi + (size_t)(r0 + erow) * T2 * G3H;
        o_p  = g_hseq + (size_t)(r0 + erow) * T2 * HID + jg0 + ej;
    }
    // DSMEM addresses of this thread's h element in all 4 CTAs (buf 0)
    unsigned hbase_local;
    {
        unsigned a;
        asm("{ .reg .u64 t; cvta.to.shared.u64 t, %1; cvt.u32.u64 %0, t; }"
            : "=r"(a) : "l"((void*)h_s));
        hbase_local = a + (unsigned)((epair * 258 + jg0 + ej) * 8 + ehalf * 4);
    }
    unsigned maddr[4];
#pragma unroll
    for (int rr = 0; rr < 4; rr++)
        asm("mapa.shared::cluster.u32 %0, %1, %2;" : "=r"(maddr[rr]) : "r"(hbase_local), "r"(rr));

    float hprev = 0.f;
    int buf = 0;

    for (int t = 0; t < T2; t++) {
        // prefetch xi[t] (consumed ~2000 cyc later; hides DRAM latency)
        float xr = 0.f, xz = 0.f, xn = 0.f;
        if (epi) {
            const float* p = xi_p + (size_t)t * G3H + jg0 + ej;
            xr = __ldg(p); xz = __ldg(p + HID); xn = __ldg(p + 2 * HID);
        }
        // matvec slice: rows packed as f32x2, weights broadcast across pairs
        unsigned long long a0 = 0, a1 = 0, a2 = 0, a3 = 0;
        const float2* hb = h_s + buf * 516 + pair * 258 + ks * 64;
        const float* wp = wbase;
#pragma unroll 4
        for (int kk = 0; kk < 64; kk++) {
            float2 hp = hb[kk];
            unsigned long long h2 = pk2(hp.x, hp.y);
            float4 wv = *(const float4*)wp;
            wp += 64;
            a0 = f2fma(h2, pk2(wv.x, wv.x), a0);
            a1 = f2fma(h2, pk2(wv.y, wv.y), a1);
            a2 = f2fma(h2, pk2(wv.z, wv.z), a2);
            a3 = f2fma(h2, pk2(wv.w, wv.w), a3);
        }
        float2* pp = part + ((g * 4 + ks) * 2 + pair) * 64 + jq * 4;
        pp[0] = upk(a0); pp[1] = upk(a1); pp[2] = upk(a2); pp[3] = upk(a3);
        __syncthreads();

        if (epi) {
            float hr = 0.f, hz = 0.f, hn = 0.f;
#pragma unroll
            for (int s = 0; s < 4; s++) {
                float2 v;
                v = part[((0 * 4 + s) * 2 + epair) * 64 + ej]; hr += ehalf ? v.y : v.x;
                v = part[((1 * 4 + s) * 2 + epair) * 64 + ej]; hz += ehalf ? v.y : v.x;
                v = part[((2 * 4 + s) * 2 + epair) * 64 + ej]; hn += ehalf ? v.y : v.x;
            }
            float r = sigm(xr + hr);
            float z = sigm(xz + hz);
            float n = tanhf(xn + r * (hn + ebhn));
            float hnew = (1.f - z) * n + z * hprev;
            hprev = hnew;
            o_p[(size_t)t * HID] = hnew;
            unsigned boff = (unsigned)((buf ^ 1) * 4128);   // 516 float2 = 4128 B
#pragma unroll
            for (int rr = 0; rr < 4; rr++)
                asm volatile("st.shared::cluster.f32 [%0], %1;"
                             :: "r"(maddr[rr] + boff), "f"(hnew) : "memory");
        }
        // release our h writes to peers; acquire theirs
        asm volatile("barrier.cluster.arrive.aligned;" ::: "memory");
        asm volatile("barrier.cluster.wait.aligned;"   ::: "memory");
        buf ^= 1;
    }
}

// ======================= proj GEMM + bias + row L2-norm =================
__global__ void k_proj(const float* __restrict__ pb, float* __restrict__ out) {
    __shared__ float a_s[32][33];
    __shared__ float b_s[32][HID];
    int tid = threadIdx.x;
    int m0 = blockIdx.x * 32;
    int cg = tid & 31, rg = tid >> 5;
    float acc[4][8] = {};
    for (int kc = 0; kc < HID; kc += 32) {
        __syncthreads();
        for (int i = tid; i < 32 * 32; i += 256) {
            int r = i >> 5, c = i & 31;
            a_s[r][c] = g_hseq[(size_t)(m0 + r) * HID + kc + c];
        }
        for (int i = tid; i < 32 * HID; i += 256) {
            int r = i >> 8, c = i & 255;
            b_s[r][c] = g_wn[(size_t)(kc + r) * HID + c];
        }
        __syncthreads();
#pragma unroll 4
        for (int k = 0; k < 32; k++) {
            float a[4], bb[8];
#pragma unroll
            for (int i = 0; i < 4; i++) a[i] = a_s[rg * 4 + i][k];
#pragma unroll
            for (int j = 0; j < 8; j++) bb[j] = b_s[k][cg + 32 * j];
#pragma unroll
            for (int i = 0; i < 4; i++)
#pragma unroll
                for (int j = 0; j < 8; j++) acc[i][j] = fmaf(a[i], bb[j], acc[i][j]);
        }
    }
#pragma unroll
    for (int i = 0; i < 4; i++) {
        float ss = 0.f;
#pragma unroll
        for (int j = 0; j < 8; j++) {
            acc[i][j] += pb[cg + 32 * j];
            ss = fmaf(acc[i][j], acc[i][j], ss);
        }
        ss += __shfl_xor_sync(0xffffffffu, ss, 1);
        ss += __shfl_xor_sync(0xffffffffu, ss, 2);
        ss += __shfl_xor_sync(0xffffffffu, ss, 4);
        ss += __shfl_xor_sync(0xffffffffu, ss, 8);
        ss += __shfl_xor_sync(0xffffffffu, ss, 16);
        float nrm = sqrtf(ss);
        float sc = (nrm > 1e-6f) ? 1.0f / (nrm + 1e-8f) : 1.0f;
        size_t row = (size_t)(m0 + rg * 4 + i);
#pragma unroll
        for (int j = 0; j < 8; j++) out[row * HID + cg + 32 * j] = acc[i][j] * sc;
    }
}

// ======================= launcher =======================================
extern "C" void kernel_launch(void* const* d_in, const int* in_sizes, int n_in,
                              void* d_out, int out_size) {
    (void)in_sizes; (void)n_in; (void)out_size;
    const float* x   = (const float*)d_in[0];
    const float* c0w = (const float*)d_in[1];
    const float* c0b = (const float*)d_in[2];
    const float* r0s = (const float*)d_in[3];
    const float* c1w = (const float*)d_in[4];
    const float* c1b = (const float*)d_in[5];
    const float* r1s = (const float*)d_in[6];
    const float* c2w = (const float*)d_in[7];
    const float* c2b = (const float*)d_in[8];
    const float* r2s = (const float*)d_in[9];
    const float* wi  = (const float*)d_in[10];
    const float* bi  = (const float*)d_in[11];
    const float* wh  = (const float*)d_in[12];
    const float* bhn = (const float*)d_in[13];
    const float* pv  = (const float*)d_in[14];
    const float* pg  = (const float*)d_in[15];
    const float* pb  = (const float*)d_in[16];
    float* out = (float*)d_out;

    cudaFuncSetAttribute(k_gru, cudaFuncAttributeMaxDynamicSharedMemorySize, GRU_SMEM);

    k_wnorm<<<1, 256>>>(pv, pg);
    k_conv0<<<dim3(8, BATCH), 256>>>(x, c0w, c0b, r0s);
    k_conv1<<<dim3(32, BATCH), 256>>>(c1w, c1b, r1s);
    k_conv2<<<dim3(32, BATCH), 256>>>(c2w, c2b, r2s);
    k_xi<<<dim3(1024, 12), 256>>>(wi, bi);
    k_gru<<<128, GRU_THREADS, GRU_SMEM>>>(wh, bhn);
    k_proj<<<2048, 256>>>(pb, out);
}